// round 16
// baseline (speedup 1.0000x reference)
#include <cuda_runtime.h>
#include <cuda_bf16.h>
#include <math.h>
#include <stdint.h>

#define NTOK  4096
#define HID   1024
#define INTER 2048
#define NEXP  8
#define TOPK  2
#define NROWS (NTOK*TOPK)

#define MT     128
// main config: CTA 128x256, 8 warps of 64x64, KSTEP 32, 3 stages x 48KB
#define NT2    256
#define KS2    32
#define STG2_B 49152
#define DSMEM  (3*STG2_B)
// fallback (static) config: R9 verbatim
#define KS1    16
#define STG1_B 16384

// ------------------------------------------------------------------ helpers
__device__ __forceinline__ uint32_t smem_u32(const void* p) {
    uint32_t a;
    asm("{ .reg .u64 t; cvta.to.shared.u64 t, %1; cvt.u32.u64 %0, t; }" : "=r"(a) : "l"(p));
    return a;
}
__device__ __forceinline__ void cp16(uint32_t s, const void* g) {
    asm volatile("cp.async.cg.shared.global [%0], [%1], 16;" :: "r"(s), "l"(g));
}
#define CP_COMMIT() asm volatile("cp.async.commit_group;" ::: "memory")
#define CP_WAIT1()  asm volatile("cp.async.wait_group 1;" ::: "memory")
#define CP_WAIT0()  asm volatile("cp.async.wait_group 0;" ::: "memory")

__device__ __forceinline__ void ldsm4(uint32_t a, uint32_t* r) {
    asm volatile("ldmatrix.sync.aligned.m8n8.x4.shared.b16 {%0,%1,%2,%3}, [%4];"
                 : "=r"(r[0]), "=r"(r[1]), "=r"(r[2]), "=r"(r[3]) : "r"(a));
}
__device__ __forceinline__ void mma16816(float* d, const uint32_t* a, const uint32_t* b) {
    asm volatile("mma.sync.aligned.m16n8k16.row.col.f32.bf16.bf16.f32 "
                 "{%0,%1,%2,%3}, {%4,%5,%6,%7}, {%8,%9}, {%0,%1,%2,%3};"
                 : "+f"(d[0]), "+f"(d[1]), "+f"(d[2]), "+f"(d[3])
                 : "r"(a[0]), "r"(a[1]), "r"(a[2]), "r"(a[3]), "r"(b[0]), "r"(b[1]));
}

// ------------------------------------------------------------------ scratch
// RULE: these symbols are ONLY referenced inside device code; NEVER passed
// as kernel arguments from kernel_launch (root cause of R4-R8).
__device__ int   g_cnt[NEXP];
__device__ int   g_off[NEXP];
__device__ int   g_cursor[NEXP];
__device__ float g_psum[NEXP];
__device__ int   g_slot_e[NROWS];
__device__ float g_slot_w[NROWS];
__device__ int   g_rowidx[NROWS];
__device__ int   g_row_tok[NROWS];

__device__ __nv_bfloat16 g_xh[(size_t)NTOK * HID];
__device__ __nv_bfloat16 g_xl[(size_t)NTOK * HID];
__device__ __nv_bfloat16 g_uh[(size_t)NEXP * INTER * HID];  // [E][N=INTER][K=HID]
__device__ __nv_bfloat16 g_ul[(size_t)NEXP * INTER * HID];
__device__ __nv_bfloat16 g_dh[(size_t)NEXP * HID * INTER];  // [E][N=HID][K=INTER]
__device__ __nv_bfloat16 g_dl[(size_t)NEXP * HID * INTER];
__device__ __nv_bfloat16 g_hh[(size_t)NROWS * INTER];
__device__ __nv_bfloat16 g_hl[(size_t)NROWS * INTER];
__device__ float         g_y [(size_t)NROWS * HID];

// ------------------------------------------------------------------ router (+ fused x hi/lo split)
__global__ __launch_bounds__(256) void k_router(const float* __restrict__ x,
                                                const float* __restrict__ rw) {
    int warp = (blockIdx.x * blockDim.x + threadIdx.x) >> 5;
    int lane = threadIdx.x & 31;
    if (warp >= NTOK) return;
    const float* xr = x + (size_t)warp * HID;
    float xv[HID / 32];
#pragma unroll
    for (int i = 0; i < HID / 32; i++) xv[i] = xr[lane + i * 32];

#pragma unroll
    for (int i = 0; i < HID / 32; i++) {
        float v = xv[i];
        __nv_bfloat16 h = __float2bfloat16(v);
        size_t o = (size_t)warp * HID + lane + i * 32;
        g_xh[o] = h;
        g_xl[o] = __float2bfloat16(v - __bfloat162float(h));
    }

    float logit[NEXP];
#pragma unroll
    for (int e = 0; e < NEXP; e++) {
        const float* w = rw + (size_t)e * HID;
        float s = 0.f;
#pragma unroll
        for (int i = 0; i < HID / 32; i++) s += xv[i] * w[lane + i * 32];
#pragma unroll
        for (int o = 16; o > 0; o >>= 1) s += __shfl_xor_sync(0xffffffffu, s, o);
        logit[e] = s;
    }
    float mx = logit[0];
#pragma unroll
    for (int e = 1; e < NEXP; e++) mx = fmaxf(mx, logit[e]);
    float p[NEXP]; float se = 0.f;
#pragma unroll
    for (int e = 0; e < NEXP; e++) { p[e] = expf(logit[e] - mx); se += p[e]; }
    float inv = 1.f / se;
#pragma unroll
    for (int e = 0; e < NEXP; e++) p[e] *= inv;
    int e0 = 0;
#pragma unroll
    for (int e = 1; e < NEXP; e++) if (p[e] > p[e0]) e0 = e;
    int e1 = -1;
#pragma unroll
    for (int e = 0; e < NEXP; e++) {
        if (e == e0) continue;
        if (e1 < 0 || p[e] > p[e1]) e1 = e;
    }
    float w0 = p[e0], w1 = p[e1];
    float ws = 1.f / (w0 + w1);
    w0 *= ws; w1 *= ws;
    if (lane == 0) {
        g_slot_e[warp * 2] = e0;  g_slot_e[warp * 2 + 1] = e1;
        g_slot_w[warp * 2] = w0;  g_slot_w[warp * 2 + 1] = w1;
        atomicAdd(&g_cnt[e0], 1); atomicAdd(&g_cnt[e1], 1);
    }
    if (lane < NEXP) atomicAdd(&g_psum[lane], p[lane]);
}

// ------------------------------------------------------------------ offsets + aux + scatter (merged, 1 block)
__global__ __launch_bounds__(1024) void k_offsets_scatter(float* __restrict__ out, int write_aux) {
    int tid = threadIdx.x;
    if (tid == 0) {
        int acc = 0; float aux = 0.f;
        for (int e = 0; e < NEXP; e++) {
            g_off[e] = acc; g_cursor[e] = acc; acc += g_cnt[e];
            float f = (float)g_cnt[e] / (float)(NTOK * TOPK);
            float P = g_psum[e] / (float)NTOK;
            aux += f * P;
        }
        if (write_aux) out[(size_t)NTOK * HID] = aux * (float)NEXP;
    }
    __syncthreads();
#pragma unroll
    for (int j = 0; j < NROWS / 1024; j++) {
        int i = tid + j * 1024;
        int e = g_slot_e[i];
        int pos = atomicAdd(&g_cursor[e], 1);
        g_rowidx[i] = pos;
        g_row_tok[pos] = i >> 1;
    }
}

// ------------------------------------------------------------------ both weight transposes+splits, one flat grid
__global__ void k_tsplit_all(const float* __restrict__ up, const float* __restrict__ dw) {
    int bid = blockIdx.x;
    bool isUp = bid < 16384;
    int lb = isUp ? bid : bid - 16384;
    const int K = isUp ? HID : INTER;
    const int N = isUp ? INTER : HID;
    const int nx = N / 32;
    int bx = lb % nx;
    int rest = lb / nx;
    int by = rest % (K / 32);
    int bz = rest / (K / 32);

    const float* Wp = (isUp ? up : dw) + (size_t)bz * K * N;
    __nv_bfloat16* Oh = isUp ? g_uh : g_dh;
    __nv_bfloat16* Ol = isUp ? g_ul : g_dl;

    __shared__ float t[32][33];
    int k0 = by * 32, n0 = bx * 32;
    int tx = threadIdx.x, ty = threadIdx.y;   // (16,16)
#pragma unroll
    for (int i = 0; i < 2; i++) {
        int kr = ty + 16 * i;
        float2 v = *(const float2*)(Wp + (size_t)(k0 + kr) * N + n0 + tx * 2);
        t[kr][tx * 2] = v.x;
        t[kr][tx * 2 + 1] = v.y;
    }
    __syncthreads();
    size_t ob = (size_t)bz * K * N;
#pragma unroll
    for (int i = 0; i < 2; i++) {
        int n = n0 + ty + 16 * i;
        float v0 = t[2 * tx][ty + 16 * i];
        float v1 = t[2 * tx + 1][ty + 16 * i];
        __nv_bfloat16 h0 = __float2bfloat16(v0);
        __nv_bfloat16 h1 = __float2bfloat16(v1);
        __nv_bfloat16 l0 = __float2bfloat16(v0 - __bfloat162float(h0));
        __nv_bfloat16 l1 = __float2bfloat16(v1 - __bfloat162float(h1));
        size_t o = ob + (size_t)n * K + k0 + 2 * tx;
        *(__nv_bfloat162*)(Oh + o) = __nv_bfloat162(h0, h1);
        *(__nv_bfloat162*)(Ol + o) = __nv_bfloat162(l0, l1);
    }
}

// ------------------------------------------------------------------ main MMA: CTA 128x256, 256 threads,
// 8 warps of 64x64 (warp grid 2m x 4n), KSTEP=32, 3 stages, one sync/chunk.
// 2-term bf16 split (Ah.Bh + Al.Bh + Ah.Bl); ldsm/mma ratio 0.5 (was 0.75).
template <bool UP>
__global__ __launch_bounds__(256, 1)
void k_mma_d() {
    constexpr int KTOT = UP ? HID : INTER;
    constexpr int NTOT = UP ? INTER : HID;
    constexpr int KCH = KTOT / KS2;
    const __nv_bfloat16* __restrict__ Ah_g = UP ? g_xh : g_hh;
    const __nv_bfloat16* __restrict__ Al_g = UP ? g_xl : g_hl;
    const __nv_bfloat16* __restrict__ Bh_g = UP ? g_uh : g_dh;
    const __nv_bfloat16* __restrict__ Bl_g = UP ? g_ul : g_dl;

    const int e   = blockIdx.z;
    const int cnt = g_cnt[e];
    const int m0  = blockIdx.y * MT;
    if (m0 >= cnt) return;
    const int off = g_off[e];
    const int n0  = blockIdx.x * NT2;

    extern __shared__ __align__(128) char dsm[];
    __shared__ int s_tok[MT];
    const uint32_t smem_base = smem_u32(dsm);

    const int tid = threadIdx.x, lane = tid & 31, wid = tid >> 5;
    const int wm = wid & 1;        // rows wm*64
    const int wn = wid >> 1;       // cols wn*64 (0..3)

    if (tid < MT) {
        int r = min(m0 + tid, cnt - 1);
        s_tok[tid] = UP ? g_row_tok[off + r] : (off + r);
    }
    __syncthreads();

    const __nv_bfloat16* Bh = Bh_g + ((size_t)e * NTOT + n0) * KTOT;
    const __nv_bfloat16* Bl = Bl_g + ((size_t)e * NTOT + n0) * KTOT;

    // stage layout (48KB): Ah[128x64B] 0 | Al 8K | Bh[256x64B] 16K | Bl 32K
    // loader: 256 threads. A: row=tid>>1, chunks (tid&1)*2+{0,1}. B: row=tid, chunks 0..3.
    const int lrA = tid >> 1;
    const int lcA0 = (tid & 1) * 2;
    const size_t arow = (size_t)s_tok[lrA] * KTOT;
    const int rB = tid;             // 0..255

    auto load_stage = [&](int ch) {
        uint32_t sb = smem_base + (ch % 3) * STG2_B;
        int kb = ch * KS2;
#pragma unroll
        for (int j = 0; j < 2; j++) {
            int c = lcA0 + j;
            uint32_t so = lrA * 64 + (uint32_t)((c ^ ((lrA >> 1) & 3)) << 4);
            int kk = kb + c * 8;
            cp16(sb + so,        Ah_g + arow + kk);
            cp16(sb + 8192 + so, Al_g + arow + kk);
        }
#pragma unroll
        for (int c = 0; c < 4; c++) {
            uint32_t so = rB * 64 + (uint32_t)((c ^ ((rB >> 1) & 3)) << 4);
            int kk = kb + c * 8;
            cp16(sb + 16384 + so, Bh + (size_t)rB * KTOT + kk);
            cp16(sb + 32768 + so, Bl + (size_t)rB * KTOT + kk);
        }
    };

    const int rowA = lane & 15;
    const int cA   = lane >> 4;
    const int rowB = (lane & 7) | ((lane >> 4) << 3);
    const int cB   = (lane >> 3) & 1;

    int rA[4], rB4[4];
#pragma unroll
    for (int mi = 0; mi < 4; mi++) rA[mi] = wm * 64 + mi * 16 + rowA;
#pragma unroll
    for (int nb = 0; nb < 4; nb++) rB4[nb] = wn * 64 + nb * 16 + rowB;

    float acc[4][8][4];
#pragma unroll
    for (int a = 0; a < 4; a++)
#pragma unroll
        for (int b = 0; b < 8; b++)
#pragma unroll
            for (int c = 0; c < 4; c++) acc[a][b][c] = 0.f;

    load_stage(0); CP_COMMIT();
    load_stage(1); CP_COMMIT();

    for (int ch = 0; ch < KCH; ch++) {
        if (ch + 1 < KCH) { CP_WAIT1(); } else { CP_WAIT0(); }
        // single barrier: group-ch data visible to all; all warps are past
        // chunk ch-1 whose slot (ch+2)%3 is overwritten below.
        __syncthreads();
        if (ch + 2 < KCH) { load_stage(ch + 2); CP_COMMIT(); }

        uint32_t sb = smem_base + (ch % 3) * STG2_B;

#pragma unroll
        for (int s = 0; s < 2; s++) {       // two K=16 subtiles per chunk
            uint32_t Af[4][4], Lf[4][4];
#pragma unroll
            for (int mi = 0; mi < 4; mi++) {
                int r = rA[mi];
                int c = (2 * s + cA) ^ ((r >> 1) & 3);
                uint32_t a = sb + r * 64 + (uint32_t)(c << 4);
                ldsm4(a, Af[mi]);
                ldsm4(a + 8192, Lf[mi]);
            }
#pragma unroll
            for (int nb = 0; nb < 4; nb++) {
                int r = rB4[nb];
                int c = (2 * s + cB) ^ ((r >> 1) & 3);
                uint32_t ba = sb + 16384 + r * 64 + (uint32_t)(c << 4);
                uint32_t Bf[4];
                ldsm4(ba, Bf);
#pragma unroll
                for (int mi = 0; mi < 4; mi++)
#pragma unroll
                    for (int h = 0; h < 2; h++) {
                        mma16816(acc[mi][nb * 2 + h], Af[mi], &Bf[h * 2]);
                        mma16816(acc[mi][nb * 2 + h], Lf[mi], &Bf[h * 2]);
                    }
                ldsm4(ba + 16384, Bf);
#pragma unroll
                for (int mi = 0; mi < 4; mi++)
#pragma unroll
                    for (int h = 0; h < 2; h++)
                        mma16816(acc[mi][nb * 2 + h], Af[mi], &Bf[h * 2]);
            }
        }
    }

    // ---- epilogue (64-row warp tiles)
    const int gID = lane >> 2;
    const int tb  = (lane & 3) * 2;
#pragma unroll
    for (int mi = 0; mi < 4; mi++) {
#pragma unroll
        for (int h = 0; h < 2; h++) {
            int m = wm * 64 + mi * 16 + gID + h * 8;
            int gr = m0 + m;
            if (gr >= cnt) continue;
            size_t rowbase = (size_t)(off + gr) * NTOT + n0 + wn * 64 + tb;
#pragma unroll
            for (int ni = 0; ni < 8; ni++) {
                float v0 = acc[mi][ni][h * 2];
                float v1 = acc[mi][ni][h * 2 + 1];
                size_t o = rowbase + ni * 8;
                if (UP) {
                    v0 = 0.5f * v0 * (1.f + erff(v0 * 0.70710678118654752f));
                    v1 = 0.5f * v1 * (1.f + erff(v1 * 0.70710678118654752f));
                    __nv_bfloat16 h0 = __float2bfloat16(v0);
                    __nv_bfloat16 h1 = __float2bfloat16(v1);
                    __nv_bfloat16 l0 = __float2bfloat16(v0 - __bfloat162float(h0));
                    __nv_bfloat16 l1 = __float2bfloat16(v1 - __bfloat162float(h1));
                    *(__nv_bfloat162*)(g_hh + o) = __nv_bfloat162(h0, h1);
                    *(__nv_bfloat162*)(g_hl + o) = __nv_bfloat162(l0, l1);
                } else {
                    *(float2*)(g_y + o) = make_float2(v0, v1);
                }
            }
        }
    }
}

// ------------------------------------------------------------------ static-smem fallback MMA (R9 verbatim config)
template <bool UP>
__global__ __launch_bounds__(256)
void k_mma_s() {
    constexpr int KTOT = UP ? HID : INTER;
    constexpr int NTOT = UP ? INTER : HID;
    constexpr int KCH = KTOT / KS1;
    const __nv_bfloat16* __restrict__ Ah_g = UP ? g_xh : g_hh;
    const __nv_bfloat16* __restrict__ Al_g = UP ? g_xl : g_hl;
    const __nv_bfloat16* __restrict__ Bh_g = UP ? g_uh : g_dh;
    const __nv_bfloat16* __restrict__ Bl_g = UP ? g_ul : g_dl;

    const int e   = blockIdx.z;
    const int cnt = g_cnt[e];
    const int m0  = blockIdx.y * MT;
    if (m0 >= cnt) return;
    const int off = g_off[e];
    const int n0  = blockIdx.x * 128;

    __shared__ __align__(128) char smem[2 * STG1_B];
    __shared__ int s_tok[MT];
    const uint32_t smem_base = smem_u32(smem);

    const int tid = threadIdx.x, lane = tid & 31, wid = tid >> 5;
    const int wm = wid & 3, wn = wid >> 2;

    if (tid < MT) {
        int r = min(m0 + tid, cnt - 1);
        s_tok[tid] = UP ? g_row_tok[off + r] : (off + r);
    }
    __syncthreads();

    const __nv_bfloat16* Bh = Bh_g + ((size_t)e * NTOT + n0) * KTOT;
    const __nv_bfloat16* Bl = Bl_g + ((size_t)e * NTOT + n0) * KTOT;

    const int lr = tid >> 1;
    const int lc = tid & 1;
    const uint32_t lso = lr * 32 + (uint32_t)((lc ^ ((lr >> 2) & 1)) << 4);

    auto load_stage = [&](int ch) {
        uint32_t sb = smem_base + (ch & 1) * STG1_B;
        int kb = ch * KS1 + lc * 8;
        cp16(sb + lso,         Ah_g + (size_t)s_tok[lr] * KTOT + kb);
        cp16(sb + 4096 + lso,  Al_g + (size_t)s_tok[lr] * KTOT + kb);
        cp16(sb + 8192 + lso,  Bh + (size_t)lr * KTOT + kb);
        cp16(sb + 12288 + lso, Bl + (size_t)lr * KTOT + kb);
    };

    const int rowA = lane & 15;
    const int cA   = lane >> 4;
    const int rowB = (lane & 7) | ((lane >> 4) << 3);
    const int cB   = (lane >> 3) & 1;

    int rA[2], rB4[4];
#pragma unroll
    for (int mi = 0; mi < 2; mi++) rA[mi] = wm * 32 + mi * 16 + rowA;
#pragma unroll
    for (int nb = 0; nb < 4; nb++) rB4[nb] = wn * 64 + nb * 16 + rowB;

    float acc[2][8][4];
#pragma unroll
    for (int a = 0; a < 2; a++)
#pragma unroll
        for (int b = 0; b < 8; b++)
#pragma unroll
            for (int c = 0; c < 4; c++) acc[a][b][c] = 0.f;

    load_stage(0); CP_COMMIT();
    load_stage(1); CP_COMMIT();

    for (int ch = 0; ch < KCH; ch++) {
        if (ch + 1 < KCH) { CP_WAIT1(); } else { CP_WAIT0(); }
        __syncthreads();

        uint32_t sb = smem_base + (ch & 1) * STG1_B;

        uint32_t Af[2][4], Lf[2][4];
#pragma unroll
        for (int mi = 0; mi < 2; mi++) {
            int r = rA[mi];
            uint32_t a = sb + r * 32 + (uint32_t)(((cA ^ ((r >> 2) & 1))) << 4);
            ldsm4(a, Af[mi]);
            ldsm4(a + 4096, Lf[mi]);
        }
#pragma unroll
        for (int nb = 0; nb < 4; nb++) {
            int r = rB4[nb];
            uint32_t ba = sb + 8192 + r * 32 + (uint32_t)(((cB ^ ((r >> 2) & 1))) << 4);
            uint32_t Bf[4];
            ldsm4(ba, Bf);
#pragma unroll
            for (int mi = 0; mi < 2; mi++)
#pragma unroll
                for (int h = 0; h < 2; h++) {
                    mma16816(acc[mi][nb * 2 + h], Af[mi], &Bf[h * 2]);
                    mma16816(acc[mi][nb * 2 + h], Lf[mi], &Bf[h * 2]);
                }
            ldsm4(ba + 4096, Bf);
#pragma unroll
            for (int mi = 0; mi < 2; mi++)
#pragma unroll
                for (int h = 0; h < 2; h++)
                    mma16816(acc[mi][nb * 2 + h], Af[mi], &Bf[h * 2]);
        }

        __syncthreads();
        if (ch + 2 < KCH) { load_stage(ch + 2); CP_COMMIT(); }
    }

    // epilogue (32-row warp tiles)
    const int gID = lane >> 2;
    const int tb  = (lane & 3) * 2;
#pragma unroll
    for (int mi = 0; mi < 2; mi++) {
#pragma unroll
        for (int h = 0; h < 2; h++) {
            int m = wm * 32 + mi * 16 + gID + h * 8;
            int gr = m0 + m;
            if (gr >= cnt) continue;
            size_t rowbase = (size_t)(off + gr) * NTOT + n0 + wn * 64 + tb;
#pragma unroll
            for (int ni = 0; ni < 8; ni++) {
                float v0 = acc[mi][ni][h * 2];
                float v1 = acc[mi][ni][h * 2 + 1];
                size_t o = rowbase + ni * 8;
                if (UP) {
                    v0 = 0.5f * v0 * (1.f + erff(v0 * 0.70710678118654752f));
                    v1 = 0.5f * v1 * (1.f + erff(v1 * 0.70710678118654752f));
                    __nv_bfloat16 h0 = __float2bfloat16(v0);
                    __nv_bfloat16 h1 = __float2bfloat16(v1);
                    __nv_bfloat16 l0 = __float2bfloat16(v0 - __bfloat162float(h0));
                    __nv_bfloat16 l1 = __float2bfloat16(v1 - __bfloat162float(h1));
                    *(__nv_bfloat162*)(g_hh + o) = __nv_bfloat162(h0, h1);
                    *(__nv_bfloat162*)(g_hl + o) = __nv_bfloat162(l0, l1);
                } else {
                    *(float2*)(g_y + o) = make_float2(v0, v1);
                }
            }
        }
    }
}

// ------------------------------------------------------------------ combine (+ counter reset for next call)
__global__ void k_combine(float* __restrict__ out) {
    int i = blockIdx.x * blockDim.x + threadIdx.x;
    int n = i >> 8;
    int c = i & 255;
    int r0 = g_rowidx[2 * n], r1 = g_rowidx[2 * n + 1];
    float w0 = g_slot_w[2 * n], w1 = g_slot_w[2 * n + 1];
    const float4* y4 = (const float4*)g_y;
    float4 y0 = y4[(size_t)r0 * 256 + c];
    float4 y1 = y4[(size_t)r1 * 256 + c];
    float4 o;
    o.x = w0 * y0.x + w1 * y1.x;
    o.y = w0 * y0.y + w1 * y1.y;
    o.z = w0 * y0.z + w1 * y1.z;
    o.w = w0 * y0.w + w1 * y1.w;
    ((float4*)out)[i] = o;
    if (blockIdx.x == 0 && threadIdx.x < NEXP) {   // reset for next launch/replay
        g_cnt[threadIdx.x] = 0;
        g_psum[threadIdx.x] = 0.f;
    }
}

// ------------------------------------------------------------------ launch
extern "C" void kernel_launch(void* const* d_in, const int* in_sizes, int n_in,
                              void* d_out, int out_size) {
    const float* x  = (const float*)d_in[0];
    const float* rw = (const float*)d_in[1];
    const float* up = (const float*)d_in[2];
    const float* dw = (const float*)d_in[3];
    float* out = (float*)d_out;

    bool dyn_ok =
        (cudaFuncSetAttribute(k_mma_d<true>,
             cudaFuncAttributeMaxDynamicSharedMemorySize, DSMEM) == cudaSuccess) &&
        (cudaFuncSetAttribute(k_mma_d<false>,
             cudaFuncAttributeMaxDynamicSharedMemorySize, DSMEM) == cudaSuccess);

    // counters are zero at first call (module init) and re-zeroed at k_combine tail
    k_router<<<NTOK / 8, 256>>>(x, rw);                       // launch 1
    k_offsets_scatter<<<1, 1024>>>(out, out_size > NTOK * HID ? 1 : 0); // launch 2
    k_tsplit_all<<<32768, dim3(16, 16)>>>(up, dw);            // launch 3

    if (dyn_ok) {
        k_mma_d<true><<<dim3(INTER / NT2, NROWS / MT, NEXP), 256, DSMEM>>>();   // launch 4 (profiled)
        k_mma_d<false><<<dim3(HID / NT2, NROWS / MT, NEXP), 256, DSMEM>>>();    // launch 5
    } else {
        k_mma_s<true><<<dim3(INTER / 128, NROWS / MT, NEXP), 256>>>();
        k_mma_s<false><<<dim3(HID / 128, NROWS / MT, NEXP), 256>>>();
    }

    k_combine<<<(NTOK * HID / 4) / 256, 256>>>(out);          // launch 6
}

// round 17
// speedup vs baseline: 1.6855x; 1.6855x over previous
#include <cuda_runtime.h>
#include <cuda_fp16.h>
#include <math.h>
#include <stdint.h>

#define NTOK  4096
#define HID   1024
#define INTER 2048
#define NEXP  8
#define TOPK  2
#define NROWS (NTOK*TOPK)

#define MT     128
// main config: CTA 128x256, 512 thr, warp 32x64 (4m x 4n), KSTEP 32, 3 stages x 32KB
#define NT2    256
#define KS2    32
#define STG2_B 32768     // Ah 8K | Al 8K | B 16K
#define DSMEM  (3*STG2_B)
// fallback static: NT 128, KSTEP 16, 2 stages x 12KB
#define KS1    16
#define STG1_B 12288     // Ah 4K | Al 4K | B 4K

// ------------------------------------------------------------------ helpers
__device__ __forceinline__ uint32_t smem_u32(const void* p) {
    uint32_t a;
    asm("{ .reg .u64 t; cvta.to.shared.u64 t, %1; cvt.u32.u64 %0, t; }" : "=r"(a) : "l"(p));
    return a;
}
__device__ __forceinline__ void cp16(uint32_t s, const void* g) {
    asm volatile("cp.async.cg.shared.global [%0], [%1], 16;" :: "r"(s), "l"(g));
}
#define CP_COMMIT() asm volatile("cp.async.commit_group;" ::: "memory")
#define CP_WAIT1()  asm volatile("cp.async.wait_group 1;" ::: "memory")
#define CP_WAIT0()  asm volatile("cp.async.wait_group 0;" ::: "memory")

__device__ __forceinline__ void ldsm4(uint32_t a, uint32_t* r) {
    asm volatile("ldmatrix.sync.aligned.m8n8.x4.shared.b16 {%0,%1,%2,%3}, [%4];"
                 : "=r"(r[0]), "=r"(r[1]), "=r"(r[2]), "=r"(r[3]) : "r"(a));
}
__device__ __forceinline__ void mma16816h(float* d, const uint32_t* a, const uint32_t* b) {
    asm volatile("mma.sync.aligned.m16n8k16.row.col.f32.f16.f16.f32 "
                 "{%0,%1,%2,%3}, {%4,%5,%6,%7}, {%8,%9}, {%0,%1,%2,%3};"
                 : "+f"(d[0]), "+f"(d[1]), "+f"(d[2]), "+f"(d[3])
                 : "r"(a[0]), "r"(a[1]), "r"(a[2]), "r"(a[3]), "r"(b[0]), "r"(b[1]));
}

// ------------------------------------------------------------------ scratch
// RULE: only referenced inside device code; NEVER passed as kernel args.
__device__ int   g_cnt[NEXP];
__device__ int   g_off[NEXP];
__device__ int   g_cursor[NEXP];
__device__ float g_psum[NEXP];
__device__ int   g_slot_e[NROWS];
__device__ float g_slot_w[NROWS];
__device__ int   g_rowidx[NROWS];
__device__ int   g_row_tok[NROWS];

__device__ __half g_xh[(size_t)NTOK * HID];                 // A hi (fp16)
__device__ __half g_xl[(size_t)NTOK * HID];                 // A lo (fp16)
__device__ __half g_uw[(size_t)NEXP * INTER * HID];         // up_w [E][N][K] fp16
__device__ __half g_dw[(size_t)NEXP * HID * INTER];         // down_w [E][N][K] fp16
__device__ __half g_hh[(size_t)NROWS * INTER];              // H hi
__device__ __half g_hl[(size_t)NROWS * INTER];              // H lo
__device__ float  g_y [(size_t)NROWS * HID];

// ------------------------------------------------------------------ router (+ fused fp16 A split)
__global__ __launch_bounds__(256) void k_router(const float* __restrict__ x,
                                                const float* __restrict__ rw) {
    int warp = (blockIdx.x * blockDim.x + threadIdx.x) >> 5;
    int lane = threadIdx.x & 31;
    if (warp >= NTOK) return;
    const float* xr = x + (size_t)warp * HID;
    float xv[HID / 32];
#pragma unroll
    for (int i = 0; i < HID / 32; i++) xv[i] = xr[lane + i * 32];

#pragma unroll
    for (int i = 0; i < HID / 32; i++) {
        float v = xv[i];
        __half h = __float2half_rn(v);
        size_t o = (size_t)warp * HID + lane + i * 32;
        g_xh[o] = h;
        g_xl[o] = __float2half_rn(v - __half2float(h));
    }

    float logit[NEXP];
#pragma unroll
    for (int e = 0; e < NEXP; e++) {
        const float* w = rw + (size_t)e * HID;
        float s = 0.f;
#pragma unroll
        for (int i = 0; i < HID / 32; i++) s += xv[i] * w[lane + i * 32];
#pragma unroll
        for (int o = 16; o > 0; o >>= 1) s += __shfl_xor_sync(0xffffffffu, s, o);
        logit[e] = s;
    }
    float mx = logit[0];
#pragma unroll
    for (int e = 1; e < NEXP; e++) mx = fmaxf(mx, logit[e]);
    float p[NEXP]; float se = 0.f;
#pragma unroll
    for (int e = 0; e < NEXP; e++) { p[e] = expf(logit[e] - mx); se += p[e]; }
    float inv = 1.f / se;
#pragma unroll
    for (int e = 0; e < NEXP; e++) p[e] *= inv;
    int e0 = 0;
#pragma unroll
    for (int e = 1; e < NEXP; e++) if (p[e] > p[e0]) e0 = e;
    int e1 = -1;
#pragma unroll
    for (int e = 0; e < NEXP; e++) {
        if (e == e0) continue;
        if (e1 < 0 || p[e] > p[e1]) e1 = e;
    }
    float w0 = p[e0], w1 = p[e1];
    float ws = 1.f / (w0 + w1);
    w0 *= ws; w1 *= ws;
    if (lane == 0) {
        g_slot_e[warp * 2] = e0;  g_slot_e[warp * 2 + 1] = e1;
        g_slot_w[warp * 2] = w0;  g_slot_w[warp * 2 + 1] = w1;
        atomicAdd(&g_cnt[e0], 1); atomicAdd(&g_cnt[e1], 1);
    }
    if (lane < NEXP) atomicAdd(&g_psum[lane], p[lane]);
}

// ------------------------------------------------------------------ offsets + aux + scatter (merged)
__global__ __launch_bounds__(1024) void k_offsets_scatter(float* __restrict__ out, int write_aux) {
    int tid = threadIdx.x;
    if (tid == 0) {
        int acc = 0; float aux = 0.f;
        for (int e = 0; e < NEXP; e++) {
            g_off[e] = acc; g_cursor[e] = acc; acc += g_cnt[e];
            float f = (float)g_cnt[e] / (float)(NTOK * TOPK);
            float P = g_psum[e] / (float)NTOK;
            aux += f * P;
        }
        if (write_aux) out[(size_t)NTOK * HID] = aux * (float)NEXP;
    }
    __syncthreads();
#pragma unroll
    for (int j = 0; j < NROWS / 1024; j++) {
        int i = tid + j * 1024;
        int e = g_slot_e[i];
        int pos = atomicAdd(&g_cursor[e], 1);
        g_rowidx[i] = pos;
        g_row_tok[pos] = i >> 1;
    }
}

// ------------------------------------------------------------------ weight transpose to fp16 [E][N][K]
__global__ void k_tsplit_all(const float* __restrict__ up, const float* __restrict__ dw) {
    int bid = blockIdx.x;
    bool isUp = bid < 16384;
    int lb = isUp ? bid : bid - 16384;
    const int K = isUp ? HID : INTER;
    const int N = isUp ? INTER : HID;
    const int nx = N / 32;
    int bx = lb % nx;
    int rest = lb / nx;
    int by = rest % (K / 32);
    int bz = rest / (K / 32);

    const float* Wp = (isUp ? up : dw) + (size_t)bz * K * N;
    __half* O = isUp ? g_uw : g_dw;

    __shared__ float t[32][33];
    int k0 = by * 32, n0 = bx * 32;
    int tx = threadIdx.x, ty = threadIdx.y;   // (16,16)
#pragma unroll
    for (int i = 0; i < 2; i++) {
        int kr = ty + 16 * i;
        float2 v = *(const float2*)(Wp + (size_t)(k0 + kr) * N + n0 + tx * 2);
        t[kr][tx * 2] = v.x;
        t[kr][tx * 2 + 1] = v.y;
    }
    __syncthreads();
    size_t ob = (size_t)bz * K * N;
#pragma unroll
    for (int i = 0; i < 2; i++) {
        int n = n0 + ty + 16 * i;
        __half h0 = __float2half_rn(t[2 * tx][ty + 16 * i]);
        __half h1 = __float2half_rn(t[2 * tx + 1][ty + 16 * i]);
        *(__half2*)(O + ob + (size_t)n * K + k0 + 2 * tx) = __half2(h0, h1);
    }
}

// ------------------------------------------------------------------ epilogue (shared)
template <bool UP>
__device__ __forceinline__ void mma_epilogue(float acc[2][8][4], int m0, int cnt, int off,
                                             int n0, int wm, int wn, int lane, int NTOT) {
    const int gID = lane >> 2;
    const int tb  = (lane & 3) * 2;
#pragma unroll
    for (int mi = 0; mi < 2; mi++) {
#pragma unroll
        for (int h = 0; h < 2; h++) {
            int m = wm * 32 + mi * 16 + gID + h * 8;
            int gr = m0 + m;
            if (gr >= cnt) continue;
            size_t rowbase = (size_t)(off + gr) * NTOT + n0 + wn * 64 + tb;
#pragma unroll
            for (int ni = 0; ni < 8; ni++) {
                float v0 = acc[mi][ni][h * 2];
                float v1 = acc[mi][ni][h * 2 + 1];
                size_t o = rowbase + ni * 8;
                if (UP) {
                    v0 = 0.5f * v0 * (1.f + erff(v0 * 0.70710678118654752f));
                    v1 = 0.5f * v1 * (1.f + erff(v1 * 0.70710678118654752f));
                    __half h0 = __float2half_rn(v0);
                    __half h1 = __float2half_rn(v1);
                    __half l0 = __float2half_rn(v0 - __half2float(h0));
                    __half l1 = __float2half_rn(v1 - __half2float(h1));
                    *(__half2*)(g_hh + o) = __half2(h0, h1);
                    *(__half2*)(g_hl + o) = __half2(l0, l1);
                } else {
                    *(float2*)(g_y + o) = make_float2(v0, v1);
                }
            }
        }
    }
}

// ------------------------------------------------------------------ main MMA: CTA 128x256, 512 thr,
// warp grid 4m x 4n of 32x64, KSTEP 32, 3 stages, one sync/chunk.
// fp16 2-term: D = Ah.B + Al.B (B single fp16)
template <bool UP>
__global__ __launch_bounds__(512, 1)
void k_mma_d() {
    constexpr int KTOT = UP ? HID : INTER;
    constexpr int NTOT = UP ? INTER : HID;
    constexpr int KCH = KTOT / KS2;
    const __half* __restrict__ Ah_g = UP ? g_xh : g_hh;
    const __half* __restrict__ Al_g = UP ? g_xl : g_hl;
    const __half* __restrict__ B_g  = UP ? g_uw : g_dw;

    const int e   = blockIdx.z;
    const int cnt = g_cnt[e];
    const int m0  = blockIdx.y * MT;
    if (m0 >= cnt) return;
    const int off = g_off[e];
    const int n0  = blockIdx.x * NT2;

    extern __shared__ __align__(128) char dsm[];
    __shared__ int s_tok[MT];
    const uint32_t smem_base = smem_u32(dsm);

    const int tid = threadIdx.x, lane = tid & 31, wid = tid >> 5;
    const int wm = wid & 3;        // rows wm*32
    const int wn = wid >> 2;       // cols wn*64

    if (tid < MT) {
        int r = min(m0 + tid, cnt - 1);
        s_tok[tid] = UP ? g_row_tok[off + r] : (off + r);
    }
    __syncthreads();

    const __half* B = B_g + ((size_t)e * NTOT + n0) * KTOT;

    // stage (32KB): Ah[128x64B] 0 | Al 8K | B[256x64B] 16K
    const int lrA = tid >> 2;            // 0..127
    const int lcA = tid & 3;             // 16B chunk
    const uint32_t soA = lrA * 64 + (uint32_t)((lcA ^ ((lrA >> 1) & 3)) << 4);
    const size_t arow = (size_t)s_tok[lrA] * KTOT;
    const int rB = tid >> 1;             // 0..255
    const int cB0 = (tid & 1) * 2;       // chunks cB0, cB0+1

    auto load_stage = [&](int ch) {
        uint32_t sb = smem_base + (ch % 3) * STG2_B;
        int kb = ch * KS2;
        cp16(sb + soA,        Ah_g + arow + kb + lcA * 8);
        cp16(sb + 8192 + soA, Al_g + arow + kb + lcA * 8);
#pragma unroll
        for (int j = 0; j < 2; j++) {
            int c = cB0 + j;
            uint32_t so = rB * 64 + (uint32_t)((c ^ ((rB >> 1) & 3)) << 4);
            cp16(sb + 16384 + so, B + (size_t)rB * KTOT + kb + c * 8);
        }
    };

    const int rowA = lane & 15;
    const int cA   = lane >> 4;
    const int rowB = (lane & 7) | ((lane >> 4) << 3);
    const int cB   = (lane >> 3) & 1;

    int rA[2], rB4[4];
#pragma unroll
    for (int mi = 0; mi < 2; mi++) rA[mi] = wm * 32 + mi * 16 + rowA;
#pragma unroll
    for (int nb = 0; nb < 4; nb++) rB4[nb] = wn * 64 + nb * 16 + rowB;

    float acc[2][8][4];
#pragma unroll
    for (int a = 0; a < 2; a++)
#pragma unroll
        for (int b = 0; b < 8; b++)
#pragma unroll
            for (int c = 0; c < 4; c++) acc[a][b][c] = 0.f;

    load_stage(0); CP_COMMIT();
    load_stage(1); CP_COMMIT();

    for (int ch = 0; ch < KCH; ch++) {
        if (ch + 1 < KCH) { CP_WAIT1(); } else { CP_WAIT0(); }
        __syncthreads();                     // single barrier per chunk
        if (ch + 2 < KCH) { load_stage(ch + 2); CP_COMMIT(); }

        uint32_t sb = smem_base + (ch % 3) * STG2_B;

#pragma unroll
        for (int s = 0; s < 2; s++) {
            uint32_t Af[2][4], Lf[2][4];
#pragma unroll
            for (int mi = 0; mi < 2; mi++) {
                int r = rA[mi];
                int c = (2 * s + cA) ^ ((r >> 1) & 3);
                uint32_t a = sb + r * 64 + (uint32_t)(c << 4);
                ldsm4(a, Af[mi]);
                ldsm4(a + 8192, Lf[mi]);
            }
#pragma unroll
            for (int nb = 0; nb < 4; nb++) {
                int r = rB4[nb];
                int c = (2 * s + cB) ^ ((r >> 1) & 3);
                uint32_t Bf[4];
                ldsm4(sb + 16384 + r * 64 + (uint32_t)(c << 4), Bf);
#pragma unroll
                for (int mi = 0; mi < 2; mi++)
#pragma unroll
                    for (int h = 0; h < 2; h++) {
                        mma16816h(acc[mi][nb * 2 + h], Af[mi], &Bf[h * 2]);
                        mma16816h(acc[mi][nb * 2 + h], Lf[mi], &Bf[h * 2]);
                    }
            }
        }
    }

    mma_epilogue<UP>(acc, m0, cnt, off, n0, wm, wn, lane, NTOT);
}

// ------------------------------------------------------------------ static fallback: NT 128, KSTEP 16, 2x12KB
template <bool UP>
__global__ __launch_bounds__(256)
void k_mma_s() {
    constexpr int KTOT = UP ? HID : INTER;
    constexpr int NTOT = UP ? INTER : HID;
    constexpr int KCH = KTOT / KS1;
    const __half* __restrict__ Ah_g = UP ? g_xh : g_hh;
    const __half* __restrict__ Al_g = UP ? g_xl : g_hl;
    const __half* __restrict__ B_g  = UP ? g_uw : g_dw;

    const int e   = blockIdx.z;
    const int cnt = g_cnt[e];
    const int m0  = blockIdx.y * MT;
    if (m0 >= cnt) return;
    const int off = g_off[e];
    const int n0  = blockIdx.x * 128;

    __shared__ __align__(128) char smem[2 * STG1_B];
    __shared__ int s_tok[MT];
    const uint32_t smem_base = smem_u32(smem);

    const int tid = threadIdx.x, lane = tid & 31, wid = tid >> 5;
    const int wm = wid & 3, wn = wid >> 2;

    if (tid < MT) {
        int r = min(m0 + tid, cnt - 1);
        s_tok[tid] = UP ? g_row_tok[off + r] : (off + r);
    }
    __syncthreads();

    const __half* B = B_g + ((size_t)e * NTOT + n0) * KTOT;

    // stage (12KB): Ah[128x32B] 0 | Al 4K | B[128x32B] 8K
    const int lr = tid >> 1;
    const int lc = tid & 1;
    const uint32_t lso = lr * 32 + (uint32_t)((lc ^ ((lr >> 2) & 1)) << 4);

    auto load_stage = [&](int ch) {
        uint32_t sb = smem_base + (ch & 1) * STG1_B;
        int kb = ch * KS1 + lc * 8;
        cp16(sb + lso,        Ah_g + (size_t)s_tok[lr] * KTOT + kb);
        cp16(sb + 4096 + lso, Al_g + (size_t)s_tok[lr] * KTOT + kb);
        cp16(sb + 8192 + lso, B + (size_t)lr * KTOT + kb);
    };

    const int rowA = lane & 15;
    const int cA   = lane >> 4;
    const int rowB = (lane & 7) | ((lane >> 4) << 3);
    const int cB   = (lane >> 3) & 1;

    int rA[2], rB4[4];
#pragma unroll
    for (int mi = 0; mi < 2; mi++) rA[mi] = wm * 32 + mi * 16 + rowA;
#pragma unroll
    for (int nb = 0; nb < 4; nb++) rB4[nb] = wn * 64 + nb * 16 + rowB;

    float acc[2][8][4];
#pragma unroll
    for (int a = 0; a < 2; a++)
#pragma unroll
        for (int b = 0; b < 8; b++)
#pragma unroll
            for (int c = 0; c < 4; c++) acc[a][b][c] = 0.f;

    load_stage(0); CP_COMMIT();
    load_stage(1); CP_COMMIT();

    for (int ch = 0; ch < KCH; ch++) {
        if (ch + 1 < KCH) { CP_WAIT1(); } else { CP_WAIT0(); }
        __syncthreads();

        uint32_t sb = smem_base + (ch & 1) * STG1_B;

        uint32_t Af[2][4], Lf[2][4];
#pragma unroll
        for (int mi = 0; mi < 2; mi++) {
            int r = rA[mi];
            uint32_t a = sb + r * 32 + (uint32_t)(((cA ^ ((r >> 2) & 1))) << 4);
            ldsm4(a, Af[mi]);
            ldsm4(a + 4096, Lf[mi]);
        }
#pragma unroll
        for (int nb = 0; nb < 4; nb++) {
            int r = rB4[nb];
            uint32_t Bf[4];
            ldsm4(sb + 8192 + r * 32 + (uint32_t)(((cB ^ ((r >> 2) & 1))) << 4), Bf);
#pragma unroll
            for (int mi = 0; mi < 2; mi++)
#pragma unroll
                for (int h = 0; h < 2; h++) {
                    mma16816h(acc[mi][nb * 2 + h], Af[mi], &Bf[h * 2]);
                    mma16816h(acc[mi][nb * 2 + h], Lf[mi], &Bf[h * 2]);
                }
        }

        __syncthreads();
        if (ch + 2 < KCH) { load_stage(ch + 2); CP_COMMIT(); }
    }

    mma_epilogue<UP>(acc, m0, cnt, off, n0, wm, wn, lane, NTOT);
}

// ------------------------------------------------------------------ combine (+ counter reset)
__global__ void k_combine(float* __restrict__ out) {
    int i = blockIdx.x * blockDim.x + threadIdx.x;
    int n = i >> 8;
    int c = i & 255;
    int r0 = g_rowidx[2 * n], r1 = g_rowidx[2 * n + 1];
    float w0 = g_slot_w[2 * n], w1 = g_slot_w[2 * n + 1];
    const float4* y4 = (const float4*)g_y;
    float4 y0 = y4[(size_t)r0 * 256 + c];
    float4 y1 = y4[(size_t)r1 * 256 + c];
    float4 o;
    o.x = w0 * y0.x + w1 * y1.x;
    o.y = w0 * y0.y + w1 * y1.y;
    o.z = w0 * y0.z + w1 * y1.z;
    o.w = w0 * y0.w + w1 * y1.w;
    ((float4*)out)[i] = o;
    if (blockIdx.x == 0 && threadIdx.x < NEXP) {
        g_cnt[threadIdx.x] = 0;
        g_psum[threadIdx.x] = 0.f;
    }
}

// ------------------------------------------------------------------ launch
extern "C" void kernel_launch(void* const* d_in, const int* in_sizes, int n_in,
                              void* d_out, int out_size) {
    const float* x  = (const float*)d_in[0];
    const float* rw = (const float*)d_in[1];
    const float* up = (const float*)d_in[2];
    const float* dw = (const float*)d_in[3];
    float* out = (float*)d_out;

    bool dyn_ok =
        (cudaFuncSetAttribute(k_mma_d<true>,
             cudaFuncAttributeMaxDynamicSharedMemorySize, DSMEM) == cudaSuccess) &&
        (cudaFuncSetAttribute(k_mma_d<false>,
             cudaFuncAttributeMaxDynamicSharedMemorySize, DSMEM) == cudaSuccess);

    k_router<<<NTOK / 8, 256>>>(x, rw);                       // launch 1
    k_offsets_scatter<<<1, 1024>>>(out, out_size > NTOK * HID ? 1 : 0); // launch 2
    k_tsplit_all<<<32768, dim3(16, 16)>>>(up, dw);            // launch 3

    if (dyn_ok) {
        k_mma_d<true><<<dim3(INTER / NT2, NROWS / MT, NEXP), 512, DSMEM>>>();   // launch 4 (profiled)
        k_mma_d<false><<<dim3(HID / NT2, NROWS / MT, NEXP), 512, DSMEM>>>();    // launch 5
    } else {
        k_mma_s<true><<<dim3(INTER / 128, NROWS / MT, NEXP), 256>>>();
        k_mma_s<false><<<dim3(HID / 128, NROWS / MT, NEXP), 256>>>();
    }

    k_combine<<<(NTOK * HID / 4) / 256, 256>>>(out);          // launch 6
}